// round 1
// baseline (speedup 1.0000x reference)
#include <cuda_runtime.h>

// Problem constants
#define TDIM   2048
#define ADIM   64
#define NTOK   (TDIM * ADIM)      // 131072 tokens
#define RAWOB  120
#define NTP    5
#define NEXP   10
#define DDIM   126                // augmented obs dim
#define HDIM   128
#define NACT   16
#define KPAD   128                // D padded to 128 for the K loop
#define TILE_M 128                // tokens per CTA tile
#define NPAD   (NTOK + NEXP * TILE_M)   // padded sorted capacity = 132352
#define NTILES (NPAD / TILE_M)          // 1034 fixed tiles

// ---------------- scratch (device globals; no allocation) ----------------
__device__ int g_counts[NEXP];
__device__ int g_cursor[NEXP];
__device__ int g_pbase[NEXP + 1];
__device__ int g_sidx[NPAD];

// ---------------- init: reset scratch each launch (determinism) ----------
__global__ void k_init() {
    int i = blockIdx.x * blockDim.x + threadIdx.x;
    if (i < NPAD) g_sidx[i] = -1;
    if (i < NEXP) { g_counts[i] = 0; g_cursor[i] = 0; }
}

// ---------------- histogram of expert picks -------------------------------
__global__ void k_hist(const int* __restrict__ pick) {
    __shared__ int h[NEXP];
    int tid = threadIdx.x;
    if (tid < NEXP) h[tid] = 0;
    __syncthreads();
    int n = blockIdx.x * blockDim.x + tid;
    if (n < NTOK) atomicAdd(&h[pick[n]], 1);
    __syncthreads();
    if (tid < NEXP && h[tid] > 0) atomicAdd(&g_counts[tid], h[tid]);
}

// ---------------- scan: padded segment bases ------------------------------
__global__ void k_scan() {
    if (threadIdx.x == 0 && blockIdx.x == 0) {
        int s = 0;
        for (int e = 0; e < NEXP; ++e) {
            g_pbase[e]  = s;
            g_cursor[e] = s;
            int c = g_counts[e];
            s += ((c + TILE_M - 1) / TILE_M) * TILE_M;
        }
        g_pbase[NEXP] = s;
    }
}

// ---------------- scatter token ids into padded per-expert segments -------
__global__ void k_scatter(const int* __restrict__ pick) {
    __shared__ int h[NEXP];
    __shared__ int base[NEXP];
    int tid = threadIdx.x;
    if (tid < NEXP) h[tid] = 0;
    __syncthreads();
    int n = blockIdx.x * blockDim.x + tid;
    int e = -1, r = 0;
    if (n < NTOK) {
        e = pick[n];
        r = atomicAdd(&h[e], 1);
    }
    __syncthreads();
    if (tid < NEXP && h[tid] > 0) base[tid] = atomicAdd(&g_cursor[tid], h[tid]);
    __syncthreads();
    if (n < NTOK) g_sidx[base[e] + r] = n;
}

// ---------------- fused main: augment + actor MLP + critic MLP ------------
// CTA: 256 threads, one 128-token tile of a single expert's padded segment.
// Register-tiled 128x128x128 fp32 GEMM (8x8 per thread), dual accumulators
// (actor W1[e] and critic Wc1 share the X operand). Second layers fused.
__global__ __launch_bounds__(256, 1)
void k_main(const float* __restrict__ obs,
            const int*   __restrict__ htype,
            const int*   __restrict__ gsel,
            const float* __restrict__ W1,  const float* __restrict__ b1,
            const float* __restrict__ W2,  const float* __restrict__ b2,
            const float* __restrict__ Wc1, const float* __restrict__ bc1,
            const float* __restrict__ Wc2, const float* __restrict__ bc2,
            float* __restrict__ out) {
    __shared__ float s_xs[16 * 132];      // X stage: [k][t], padded row 132
    __shared__ float s_ws[16 * 132];      // W1 stage: [k][j]
    __shared__ float s_wcs[16 * 132];     // Wc1 stage: [k][j]
    __shared__ float s_w2[HDIM * NACT];   // W2[e]
    __shared__ float s_b1[HDIM];
    __shared__ float s_bc1[HDIM];
    __shared__ float s_wc2[HDIM];
    __shared__ float s_ls[TILE_M * NACT]; // logits accumulation tile
    __shared__ int   s_idx[TILE_M];
    __shared__ int   s_e;

    const int tid = threadIdx.x;
    const int ts  = blockIdx.x * TILE_M;

    if (tid == 0) {
        int e = -1;
        #pragma unroll
        for (int q = 0; q < NEXP; ++q)
            if (ts >= g_pbase[q] && ts < g_pbase[q + 1]) e = q;
        s_e = e;
    }
    if (tid < TILE_M) s_idx[tid] = g_sidx[ts + tid];
    __syncthreads();
    const int e = s_e;
    if (e < 0) return;  // tile beyond all segments (uniform exit)

    // per-CTA constants
    for (int i = tid; i < HDIM * NACT; i += 256) {
        s_w2[i] = W2[e * HDIM * NACT + i];
        s_ls[i] = 0.0f;
    }
    if (tid < HDIM) {
        s_b1[tid]  = b1[e * HDIM + tid];
        s_bc1[tid] = bc1[tid];
        s_wc2[tid] = Wc2[tid];
    }

    float acc[8][8];   // actor hidden accumulators
    float ac2[8][8];   // critic hidden accumulators
    #pragma unroll
    for (int i = 0; i < 8; ++i)
        #pragma unroll
        for (int j = 0; j < 8; ++j) { acc[i][j] = 0.0f; ac2[i][j] = 0.0f; }

    const int ti0 = (tid >> 4) << 3;   // token sub-tile base (0..120)
    const int tj0 = (tid & 15) << 3;   // hidden sub-tile base (0..120)

    for (int kb = 0; kb < KPAD; kb += 16) {
        __syncthreads();
        // --- stage X (with on-the-fly augmentation), warp-friendly gather ---
        {
            int k  = tid & 15;
            int tl = tid >> 4;
            int kg = kb + k;
            #pragma unroll
            for (int it = 0; it < 8; ++it) {
                int t   = it * 16 + tl;
                int tok = s_idx[t];
                float v = 0.0f;
                if (tok >= 0 && kg < DDIM) {
                    if (kg < RAWOB) {
                        v = obs[tok * RAWOB + kg];
                    } else if (kg == RAWOB) {
                        v = (float)htype[tok];
                    } else {
                        int i  = kg - (RAWOB + 1);
                        int ht = htype[tok];
                        v = (i == ht) ? -1.0f
                                      : (float)gsel[(tok >> 6) * NTP + i];
                    }
                }
                s_xs[k * 132 + t] = v;
            }
        }
        // --- stage W1[e] and Wc1 rows kb..kb+15 (zero pad rows >= 126) ----
        #pragma unroll
        for (int it = 0; it < 8; ++it) {
            int idx = tid + it * 256;
            int k   = idx >> 7;
            int j   = idx & 127;
            int row = kb + k;
            float w = 0.0f, wc = 0.0f;
            if (row < DDIM) {
                w  = W1[(e * DDIM + row) * HDIM + j];
                wc = Wc1[row * HDIM + j];
            }
            s_ws[k * 132 + j]  = w;
            s_wcs[k * 132 + j] = wc;
        }
        __syncthreads();
        // --- compute 16 K-steps ------------------------------------------
        #pragma unroll
        for (int k = 0; k < 16; ++k) {
            float4 xa = *(const float4*)&s_xs[k * 132 + ti0];
            float4 xb = *(const float4*)&s_xs[k * 132 + ti0 + 4];
            float4 wa = *(const float4*)&s_ws[k * 132 + tj0];
            float4 wb = *(const float4*)&s_ws[k * 132 + tj0 + 4];
            float4 ca = *(const float4*)&s_wcs[k * 132 + tj0];
            float4 cb = *(const float4*)&s_wcs[k * 132 + tj0 + 4];
            float xv[8] = {xa.x, xa.y, xa.z, xa.w, xb.x, xb.y, xb.z, xb.w};
            float wv[8] = {wa.x, wa.y, wa.z, wa.w, wb.x, wb.y, wb.z, wb.w};
            float cv[8] = {ca.x, ca.y, ca.z, ca.w, cb.x, cb.y, cb.z, cb.w};
            #pragma unroll
            for (int i = 0; i < 8; ++i)
                #pragma unroll
                for (int j = 0; j < 8; ++j) {
                    acc[i][j] = fmaf(xv[i], wv[j], acc[i][j]);
                    ac2[i][j] = fmaf(xv[i], cv[j], ac2[i][j]);
                }
        }
    }

    // --- bias + ReLU -----------------------------------------------------
    #pragma unroll
    for (int i = 0; i < 8; ++i)
        #pragma unroll
        for (int j = 0; j < 8; ++j) {
            acc[i][j] = fmaxf(acc[i][j] + s_b1[tj0 + j], 0.0f);
            ac2[i][j] = fmaxf(ac2[i][j] + s_bc1[tj0 + j], 0.0f);
        }

    // --- critic head: value[t] = hc . Wc2 + bc2 (16-lane shfl reduce) ----
    {
        float bc2v = bc2[0];
        #pragma unroll
        for (int i = 0; i < 8; ++i) {
            float s = 0.0f;
            #pragma unroll
            for (int j = 0; j < 8; ++j)
                s = fmaf(ac2[i][j], s_wc2[tj0 + j], s);
            s += __shfl_xor_sync(0xffffffffu, s, 8);
            s += __shfl_xor_sync(0xffffffffu, s, 4);
            s += __shfl_xor_sync(0xffffffffu, s, 2);
            s += __shfl_xor_sync(0xffffffffu, s, 1);
            if ((tid & 15) == 0) {
                int tok = s_idx[ti0 + i];
                if (tok >= 0) out[NTOK * NACT + tok] = s + bc2v;
            }
        }
    }

    // --- actor head: logits = h @ W2[e] + b2[e] --------------------------
    #pragma unroll
    for (int i = 0; i < 8; ++i) {
        #pragma unroll
        for (int o = 0; o < NACT; ++o) {
            float s = 0.0f;
            #pragma unroll
            for (int j = 0; j < 8; ++j)
                s = fmaf(acc[i][j], s_w2[(tj0 + j) * NACT + o], s);
            atomicAdd(&s_ls[(ti0 + i) * NACT + o], s);
        }
    }
    __syncthreads();
    for (int idx = tid; idx < TILE_M * NACT; idx += 256) {
        int t   = idx >> 4;
        int o   = idx & 15;
        int tok = s_idx[t];
        if (tok >= 0) out[tok * NACT + o] = s_ls[idx] + b2[e * NACT + o];
    }
}

// ---------------- launch ---------------------------------------------------
extern "C" void kernel_launch(void* const* d_in, const int* in_sizes, int n_in,
                              void* d_out, int out_size) {
    const float* obs   = (const float*)d_in[0];
    const int*   pick  = (const int*)  d_in[1];
    const int*   htype = (const int*)  d_in[2];
    const int*   gsel  = (const int*)  d_in[3];
    const float* W1    = (const float*)d_in[4];
    const float* b1    = (const float*)d_in[5];
    const float* W2    = (const float*)d_in[6];
    const float* b2    = (const float*)d_in[7];
    const float* Wc1   = (const float*)d_in[8];
    const float* bc1   = (const float*)d_in[9];
    const float* Wc2   = (const float*)d_in[10];
    const float* bc2   = (const float*)d_in[11];
    float* out = (float*)d_out;

    k_init   <<<(NPAD + 255) / 256, 256>>>();
    k_hist   <<<(NTOK + 255) / 256, 256>>>(pick);
    k_scan   <<<1, 1>>>();
    k_scatter<<<(NTOK + 255) / 256, 256>>>(pick);
    k_main   <<<NTILES, 256>>>(obs, htype, gsel,
                               W1, b1, W2, b2, Wc1, bc1, Wc2, bc2, out);
}

// round 3
// speedup vs baseline: 5.1585x; 5.1585x over previous
#include <cuda_runtime.h>
#include <cuda_bf16.h>
#include <cstdint>

// ---------------- problem constants ----------------
#define TDIM   2048
#define ADIM   64
#define NTOK   (TDIM * ADIM)          // 131072
#define RAWOB  120
#define NTP    5
#define NEXP   10
#define DDIM   126
#define HDIM   128
#define NACT   16
#define TILE_M 128
#define NPAD   (NTOK + NEXP * TILE_M) // 132352
#define NTILES (NPAD / TILE_M)        // 1034

// dynamic smem: six 128x128 bf16 tiles, 256B rows, XOR-swizzled (32KB each)
#define AH_OFF   0
#define AL_OFF   32768
#define B1H_OFF  65536
#define B1L_OFF  98304
#define BCH_OFF  131072
#define BCL_OFF  163840
#define DYN_SMEM 196608
// after mainloop, regions are reused for hidden activations:
//   actor hidden hi/lo -> AH/AL ; critic hidden hi/lo -> B1H/B1L

// ---------------- scratch ----------------
__device__ int g_counts[NEXP];
__device__ int g_cursor[NEXP];
__device__ int g_pbase[NEXP + 1];
__device__ int g_sidx[NPAD];

// ---------------- prep kernels ----------------
__global__ void k_init() {
    int i = blockIdx.x * blockDim.x + threadIdx.x;
    if (i < NPAD) g_sidx[i] = -1;
    if (i < NEXP) { g_counts[i] = 0; g_cursor[i] = 0; }
}
__global__ void k_hist(const int* __restrict__ pick) {
    __shared__ int h[NEXP];
    int tid = threadIdx.x;
    if (tid < NEXP) h[tid] = 0;
    __syncthreads();
    int n = blockIdx.x * blockDim.x + tid;
    if (n < NTOK) atomicAdd(&h[pick[n]], 1);
    __syncthreads();
    if (tid < NEXP && h[tid] > 0) atomicAdd(&g_counts[tid], h[tid]);
}
__global__ void k_scan() {
    if (threadIdx.x == 0 && blockIdx.x == 0) {
        int s = 0;
        for (int e = 0; e < NEXP; ++e) {
            g_pbase[e]  = s;
            g_cursor[e] = s;
            int c = g_counts[e];
            s += ((c + TILE_M - 1) / TILE_M) * TILE_M;
        }
        g_pbase[NEXP] = s;
    }
}
__global__ void k_scatter(const int* __restrict__ pick) {
    __shared__ int h[NEXP];
    __shared__ int base[NEXP];
    int tid = threadIdx.x;
    if (tid < NEXP) h[tid] = 0;
    __syncthreads();
    int n = blockIdx.x * blockDim.x + tid;
    int e = -1, r = 0;
    if (n < NTOK) { e = pick[n]; r = atomicAdd(&h[e], 1); }
    __syncthreads();
    if (tid < NEXP && h[tid] > 0) base[tid] = atomicAdd(&g_cursor[tid], h[tid]);
    __syncthreads();
    if (n < NTOK) g_sidx[base[e] + r] = n;
}

// ---------------- warp MMA helpers (plain compute_103 PTX) ----------------
__device__ __forceinline__ uint32_t smem_u32(const void* p) {
    uint32_t a;
    asm("{ .reg .u64 t; cvta.to.shared.u64 t, %1; cvt.u32.u64 %0, t; }"
        : "=r"(a) : "l"(p));
    return a;
}
__device__ __forceinline__ void ldsm4(uint32_t* r, uint32_t addr) {
    asm volatile("ldmatrix.sync.aligned.m8n8.x4.shared.b16 {%0,%1,%2,%3}, [%4];"
                 : "=r"(r[0]), "=r"(r[1]), "=r"(r[2]), "=r"(r[3]) : "r"(addr));
}
__device__ __forceinline__ void mma16816(float* d, const uint32_t* a,
                                         uint32_t b0, uint32_t b1) {
    asm volatile(
        "mma.sync.aligned.m16n8k16.row.col.f32.bf16.bf16.f32 "
        "{%0,%1,%2,%3}, {%4,%5,%6,%7}, {%8,%9}, {%0,%1,%2,%3};"
        : "+f"(d[0]), "+f"(d[1]), "+f"(d[2]), "+f"(d[3])
        : "r"(a[0]), "r"(a[1]), "r"(a[2]), "r"(a[3]), "r"(b0), "r"(b1));
}
// tile element byte offset: 256B rows, 16B chunks XOR-swizzled by row
__device__ __forceinline__ uint32_t toff(int row, int k) {
    return (uint32_t)(row * 256 + (((k >> 3) ^ (row & 7)) << 4) + (k & 7) * 2);
}
__device__ __forceinline__ void cvt_hilo(float a, float b, uint32_t& hi, uint32_t& lo) {
    __nv_bfloat16 ah = __float2bfloat16(a), bh = __float2bfloat16(b);
    __nv_bfloat16 al = __float2bfloat16(a - __bfloat162float(ah));
    __nv_bfloat16 bl = __float2bfloat16(b - __bfloat162float(bh));
    hi = (uint32_t)__bfloat16_as_ushort(ah) | ((uint32_t)__bfloat16_as_ushort(bh) << 16);
    lo = (uint32_t)__bfloat16_as_ushort(al) | ((uint32_t)__bfloat16_as_ushort(bl) << 16);
}

// ---------------- fused main ----------------
__global__ __launch_bounds__(512, 1)
void k_main(const float* __restrict__ obs,
            const int*   __restrict__ htype,
            const int*   __restrict__ gsel,
            const float* __restrict__ W1,  const float* __restrict__ b1,
            const float* __restrict__ W2,  const float* __restrict__ b2,
            const float* __restrict__ Wc1, const float* __restrict__ bc1,
            const float* __restrict__ Wc2, const float* __restrict__ bc2,
            float* __restrict__ out) {
    extern __shared__ char dsm[];
    // small second-layer weight tiles (16 rows x 256B), staged pre-mainloop
    __shared__ __align__(1024) unsigned char s_w2h[16 * 256];
    __shared__ __align__(1024) unsigned char s_w2l[16 * 256];
    __shared__ __align__(1024) unsigned char s_wch[16 * 256];
    __shared__ __align__(1024) unsigned char s_wcl[16 * 256];
    __shared__ float s_b1[HDIM], s_bc1[HDIM], s_b2[NACT];
    __shared__ int   s_idx[TILE_M];
    __shared__ int   s_e;

    const int tid    = threadIdx.x;
    const int wid    = tid >> 5;
    const int lane   = tid & 31;
    const int lane15 = lane & 15;
    const int laneh  = lane >> 4;
    const int g      = lane >> 2;     // row group within m8n8 frag
    const int q4     = lane & 3;      // col pair index
    const int ts     = blockIdx.x * TILE_M;

    if (tid == 0) {
        int e = -1;
        #pragma unroll
        for (int q = 0; q < NEXP; ++q)
            if (ts >= g_pbase[q] && ts < g_pbase[q + 1]) e = q;
        s_e = e;
    }
    if (tid < TILE_M) s_idx[tid] = g_sidx[ts + tid];
    __syncthreads();
    const int e = s_e;
    if (e < 0) return;

    const uint32_t db = smem_u32(dsm);

    // ---- biases ----
    if (tid < HDIM) {
        s_b1[tid]  = b1[e * HDIM + tid];
        s_bc1[tid] = bc1[tid];
    }
    if (tid < NACT) s_b2[tid] = b2[e * NACT + tid];

    // ---- stage W2^T [o][j] and Wc2 [row0][j] hi/lo (static tiles) ----
    for (int it = tid; it < 16 * 64; it += 512) {     // (o, jpair)
        int o = it >> 6, jp = it & 63, j0 = jp * 2;
        float a = W2[(e * HDIM + j0) * NACT + o];
        float c = W2[(e * HDIM + j0 + 1) * NACT + o];
        uint32_t hi, lo; cvt_hilo(a, c, hi, lo);
        uint32_t off = toff(o, j0);
        *(uint32_t*)(s_w2h + off) = hi;
        *(uint32_t*)(s_w2l + off) = lo;
        float wa = (o == 0) ? Wc2[j0] : 0.0f;
        float wb = (o == 0) ? Wc2[j0 + 1] : 0.0f;
        cvt_hilo(wa, wb, hi, lo);
        *(uint32_t*)(s_wch + off) = hi;
        *(uint32_t*)(s_wcl + off) = lo;
    }

    // ---- stage A (augmented obs) hi/lo, swizzled [t][k] ----
    for (int it = tid; it < TILE_M * 64; it += 512) { // (t, kpair)
        int t = it >> 6, kp = it & 63, k0 = kp * 2;
        int tok = s_idx[t];
        float v0 = 0.0f, v1 = 0.0f;
        if (tok >= 0) {
            int ht = htype[tok];
            #pragma unroll
            for (int u = 0; u < 2; ++u) {
                int k = k0 + u;
                float v = 0.0f;
                if (k < RAWOB)       v = obs[tok * RAWOB + k];
                else if (k == RAWOB) v = (float)ht;
                else if (k < DDIM) {
                    int i = k - (RAWOB + 1);
                    v = (i == ht) ? -1.0f : (float)gsel[(tok >> 6) * NTP + i];
                }
                if (u == 0) v0 = v; else v1 = v;
            }
        }
        uint32_t hi, lo; cvt_hilo(v0, v1, hi, lo);
        uint32_t off = toff(t, k0);
        *(uint32_t*)(dsm + AH_OFF + off) = hi;
        *(uint32_t*)(dsm + AL_OFF + off) = lo;
    }

    // ---- stage W1[e] and Wc1 as B tiles [n][k] hi/lo ----
    {
        const float* w1p = W1 + (size_t)e * DDIM * HDIM;
        for (int it = tid; it < 64 * 128; it += 512) { // (kpair, n)
            int n = it & 127, kp = it >> 7, k0 = kp * 2;
            float a0 = (k0     < DDIM) ? w1p[k0 * HDIM + n]       : 0.0f;
            float a1 = (k0 + 1 < DDIM) ? w1p[(k0 + 1) * HDIM + n] : 0.0f;
            float c0 = (k0     < DDIM) ? Wc1[k0 * HDIM + n]       : 0.0f;
            float c1 = (k0 + 1 < DDIM) ? Wc1[(k0 + 1) * HDIM + n] : 0.0f;
            uint32_t off = toff(n, k0), hi, lo;
            cvt_hilo(a0, a1, hi, lo);
            *(uint32_t*)(dsm + B1H_OFF + off) = hi;
            *(uint32_t*)(dsm + B1L_OFF + off) = lo;
            cvt_hilo(c0, c1, hi, lo);
            *(uint32_t*)(dsm + BCH_OFF + off) = hi;
            *(uint32_t*)(dsm + BCL_OFF + off) = lo;
        }
    }
    __syncthreads();

    // ---- mainloop: 128x128x128 bf16 hi/lo (3 passes), actor | critic ----
    const int  isActor = (wid < 8);
    const int  wq = wid & 7;
    const int  m0 = (wq & 3) * 32;
    const int  n0 = (wq >> 2) * 64;

    const int arow0 = m0 + lane15,  arow1 = arow0 + 16;
    const uint32_t aoff0 = arow0 * 256, aoff1 = arow1 * 256;
    const int r7a0 = arow0 & 7, r7a1 = arow1 & 7;
    int      brow[4];
    uint32_t boffv[4];
    int      r7b[4];
    #pragma unroll
    for (int qb = 0; qb < 4; ++qb) {
        brow[qb]  = n0 + qb * 16 + lane15;
        boffv[qb] = brow[qb] * 256;
        r7b[qb]   = brow[qb] & 7;
    }

    float acc[2][8][4];
    #pragma unroll
    for (int i = 0; i < 2; ++i)
        #pragma unroll
        for (int j = 0; j < 8; ++j)
            #pragma unroll
            for (int c = 0; c < 4; ++c) acc[i][j][c] = 0.0f;

    const uint32_t aB[3] = {db + AH_OFF, db + AH_OFF, db + AL_OFF};
    const uint32_t bB[3] = {
        isActor ? db + B1H_OFF : db + BCH_OFF,
        isActor ? db + B1L_OFF : db + BCL_OFF,
        isActor ? db + B1H_OFF : db + BCH_OFF};

    #pragma unroll
    for (int p = 0; p < 3; ++p) {
        const uint32_t ab = aB[p], bb = bB[p];
        #pragma unroll
        for (int ks = 0; ks < 8; ++ks) {
            const int c0 = 2 * ks + laneh;
            uint32_t af0[4], af1[4];
            ldsm4(af0, ab + aoff0 + (uint32_t)((c0 ^ r7a0) << 4));
            ldsm4(af1, ab + aoff1 + (uint32_t)((c0 ^ r7a1) << 4));
            #pragma unroll
            for (int qb = 0; qb < 4; ++qb) {
                uint32_t bf[4];
                ldsm4(bf, bb + boffv[qb] + (uint32_t)((c0 ^ r7b[qb]) << 4));
                mma16816(acc[0][2 * qb],     af0, bf[0], bf[2]);
                mma16816(acc[0][2 * qb + 1], af0, bf[1], bf[3]);
                mma16816(acc[1][2 * qb],     af1, bf[0], bf[2]);
                mma16816(acc[1][2 * qb + 1], af1, bf[1], bf[3]);
            }
        }
    }
    __syncthreads();   // everyone done reading weight tiles

    // ---- bias + relu, write hidden hi/lo back (actor->AH/AL, critic->B1H/B1L)
    {
        const uint32_t hH = isActor ? db + AH_OFF  : db + B1H_OFF;
        const uint32_t hL = isActor ? db + AL_OFF  : db + B1L_OFF;
        const float*   bs = isActor ? s_b1 : s_bc1;
        #pragma unroll
        for (int mt = 0; mt < 2; ++mt) {
            #pragma unroll
            for (int nf = 0; nf < 8; ++nf) {
                const int col = n0 + 8 * nf + 2 * q4;
                const float bA = bs[col], bBv = bs[col + 1];
                const int r0 = m0 + 16 * mt + g, r1 = r0 + 8;
                float v0 = fmaxf(acc[mt][nf][0] + bA, 0.0f);
                float v1 = fmaxf(acc[mt][nf][1] + bBv, 0.0f);
                uint32_t hi, lo; cvt_hilo(v0, v1, hi, lo);
                uint32_t off = toff(r0, col);
                *(uint32_t*)(hH - db + dsm + off) = hi;
                *(uint32_t*)(hL - db + dsm + off) = lo;
                v0 = fmaxf(acc[mt][nf][2] + bA, 0.0f);
                v1 = fmaxf(acc[mt][nf][3] + bBv, 0.0f);
                cvt_hilo(v0, v1, hi, lo);
                off = toff(r1, col);
                *(uint32_t*)(hH - db + dsm + off) = hi;
                *(uint32_t*)(hL - db + dsm + off) = lo;
            }
        }
    }
    __syncthreads();

    // ---- phase 2: logits = h@W2 (actor), value = h@Wc2 (critic), via MMA ----
    {
        const int arow = wq * 16 + lane15;
        const uint32_t aoff = arow * 256;
        const int r7 = arow & 7;
        const int browp = lane15;
        const uint32_t boffp = browp * 256;
        const int r7p = browp & 7;

        const uint32_t a2B[3] = {
            isActor ? db + AH_OFF  : db + B1H_OFF,
            isActor ? db + AH_OFF  : db + B1H_OFF,
            isActor ? db + AL_OFF  : db + B1L_OFF};
        const uint32_t w2h = smem_u32(s_w2h), w2l = smem_u32(s_w2l);
        const uint32_t wch = smem_u32(s_wch), wcl = smem_u32(s_wcl);
        const uint32_t b2B[3] = {
            isActor ? w2h : wch, isActor ? w2l : wcl, isActor ? w2h : wch};

        float ac2[2][4];
        #pragma unroll
        for (int i = 0; i < 2; ++i)
            #pragma unroll
            for (int c = 0; c < 4; ++c) ac2[i][c] = 0.0f;

        #pragma unroll
        for (int p = 0; p < 3; ++p) {
            #pragma unroll
            for (int ks = 0; ks < 8; ++ks) {
                const int c0 = 2 * ks + laneh;
                uint32_t af[4], bf[4];
                ldsm4(af, a2B[p] + aoff + (uint32_t)((c0 ^ r7) << 4));
                ldsm4(bf, b2B[p] + boffp + (uint32_t)((c0 ^ r7p) << 4));
                mma16816(ac2[0], af, bf[0], bf[2]);
                if (isActor) mma16816(ac2[1], af, bf[1], bf[3]);
            }
        }

        const int r0 = wq * 16 + g, r1 = r0 + 8;
        const int tok0 = s_idx[r0], tok1 = s_idx[r1];
        if (isActor) {
            #pragma unroll
            for (int nf = 0; nf < 2; ++nf) {
                const int cl = 8 * nf + 2 * q4;
                const float bA = s_b2[cl], bBv = s_b2[cl + 1];
                if (tok0 >= 0) {
                    float2 v = {ac2[nf][0] + bA, ac2[nf][1] + bBv};
                    *(float2*)(out + (size_t)tok0 * NACT + cl) = v;
                }
                if (tok1 >= 0) {
                    float2 v = {ac2[nf][2] + bA, ac2[nf][3] + bBv};
                    *(float2*)(out + (size_t)tok1 * NACT + cl) = v;
                }
            }
        } else if (q4 == 0) {
            const float bcv = bc2[0];
            if (tok0 >= 0) out[(size_t)NTOK * NACT + tok0] = ac2[0][0] + bcv;
            if (tok1 >= 0) out[(size_t)NTOK * NACT + tok1] = ac2[0][2] + bcv;
        }
    }
}

// ---------------- launch ----------------
extern "C" void kernel_launch(void* const* d_in, const int* in_sizes, int n_in,
                              void* d_out, int out_size) {
    const float* obs   = (const float*)d_in[0];
    const int*   pick  = (const int*)  d_in[1];
    const int*   htype = (const int*)  d_in[2];
    const int*   gsel  = (const int*)  d_in[3];
    const float* W1    = (const float*)d_in[4];
    const float* b1    = (const float*)d_in[5];
    const float* W2    = (const float*)d_in[6];
    const float* b2    = (const float*)d_in[7];
    const float* Wc1   = (const float*)d_in[8];
    const float* bc1   = (const float*)d_in[9];
    const float* Wc2   = (const float*)d_in[10];
    const float* bc2   = (const float*)d_in[11];
    float* out = (float*)d_out;

    cudaFuncSetAttribute(k_main, cudaFuncAttributeMaxDynamicSharedMemorySize, DYN_SMEM);

    k_init   <<<(NPAD + 255) / 256, 256>>>();
    k_hist   <<<(NTOK + 255) / 256, 256>>>(pick);
    k_scan   <<<1, 1>>>();
    k_scatter<<<(NTOK + 255) / 256, 256>>>(pick);
    k_main   <<<NTILES, 512, DYN_SMEM>>>(obs, htype, gsel,
                                         W1, b1, W2, b2, Wc1, bc1, Wc2, bc2, out);
}

// round 6
// speedup vs baseline: 7.7068x; 1.4940x over previous
#include <cuda_runtime.h>
#include <cuda_bf16.h>
#include <cstdint>

// ---------------- problem constants ----------------
#define TDIM   2048
#define ADIM   64
#define NTOK   (TDIM * ADIM)          // 131072
#define RAWOB  120
#define NTP    5
#define NEXP   10
#define DDIM   126
#define HDIM   128
#define NACT   16
#define TILE_M 128
#define NPAD   (NTOK + NEXP * TILE_M) // 132352
#define NTILES (NPAD / TILE_M)        // 1034

// dynamic smem: six 128x128 bf16 tiles, 256B rows, XOR-swizzled (32KB each)
#define AH_OFF   0
#define AL_OFF   32768
#define B1H_OFF  65536
#define B1L_OFF  98304
#define BCH_OFF  131072
#define BCL_OFF  163840
#define DYN_SMEM 196608

// ---------------- scratch ----------------
__device__ int g_counts[NEXP];
__device__ int g_cursor[NEXP];
__device__ int g_pbase[NEXP + 1];
__device__ int g_sidx[NPAD];
__device__ unsigned int g_tick;

// pre-swizzled bf16 hi/lo weight tiles (exact smem byte layout)
__device__ uint4 g_w1h[NEXP * 2048];   // 32KB per expert
__device__ uint4 g_w1l[NEXP * 2048];
__device__ uint4 g_wch[2048];
__device__ uint4 g_wcl[2048];
__device__ uint4 g_w2h[NEXP * 256];    // 4KB per expert (16x128 tile)
__device__ uint4 g_w2l[NEXP * 256];
__device__ uint4 g_wc2h[256];
__device__ uint4 g_wc2l[256];

// tile element byte offset: 256B rows, 16B chunks XOR-swizzled by row
__device__ __forceinline__ uint32_t toff(int row, int k) {
    return (uint32_t)(row * 256 + (((k >> 3) ^ (row & 7)) << 4) + (k & 7) * 2);
}
__device__ __forceinline__ void cvt_hilo(float a, float b, uint32_t& hi, uint32_t& lo) {
    __nv_bfloat162 h2 = __floats2bfloat162_rn(a, b);
    float2 back = __bfloat1622float2(h2);
    __nv_bfloat162 l2 = __floats2bfloat162_rn(a - back.x, b - back.y);
    hi = reinterpret_cast<uint32_t&>(h2);
    lo = reinterpret_cast<uint32_t&>(l2);
}

// ---------------- k_prep: weight tiles + scratch zeroing ----------------
__global__ void k_prep(const float* __restrict__ W1,  const float* __restrict__ W2,
                       const float* __restrict__ Wc1, const float* __restrict__ Wc2) {
    const int e   = blockIdx.x;           // 0..NEXP-1 experts, NEXP = critic
    const int tid = threadIdx.x;
    if (e == 0 && tid < 32) {
        if (tid < NEXP) { g_counts[tid] = 0; g_cursor[tid] = 0; }
        if (tid == 31) g_tick = 0;
    }
    uint32_t* d1h; uint32_t* d1l; const float* w1p;
    if (e < NEXP) {
        d1h = (uint32_t*)g_w1h + e * 8192;
        d1l = (uint32_t*)g_w1l + e * 8192;
        w1p = W1 + (size_t)e * DDIM * HDIM;
    } else {
        d1h = (uint32_t*)g_wch;
        d1l = (uint32_t*)g_wcl;
        w1p = Wc1;
    }
    // layer-1 tile: [n][k] hi/lo, swizzled
    for (int it = tid; it < 64 * 128; it += 256) {
        int n = it & 127, kp = it >> 7, k0 = kp * 2;
        float a0 = (k0     < DDIM) ? w1p[k0 * HDIM + n]       : 0.0f;
        float a1 = (k0 + 1 < DDIM) ? w1p[(k0 + 1) * HDIM + n] : 0.0f;
        uint32_t hi, lo; cvt_hilo(a0, a1, hi, lo);
        uint32_t o4 = toff(n, k0) >> 2;
        d1h[o4] = hi; d1l[o4] = lo;
    }
    // layer-2 tile: 16 rows x 128 cols [o][j] hi/lo, swizzled
    uint32_t* d2h = (e < NEXP) ? (uint32_t*)g_w2h + e * 1024 : (uint32_t*)g_wc2h;
    uint32_t* d2l = (e < NEXP) ? (uint32_t*)g_w2l + e * 1024 : (uint32_t*)g_wc2l;
    for (int it = tid; it < 16 * 64; it += 256) {
        int o = it >> 6, jp = it & 63, j0 = jp * 2;
        float a, b;
        if (e < NEXP) {
            a = W2[((size_t)e * HDIM + j0) * NACT + o];
            b = W2[((size_t)e * HDIM + j0 + 1) * NACT + o];
        } else {
            a = (o == 0) ? Wc2[j0] : 0.0f;
            b = (o == 0) ? Wc2[j0 + 1] : 0.0f;
        }
        uint32_t hi, lo; cvt_hilo(a, b, hi, lo);
        uint32_t o4 = toff(o, j0) >> 2;
        d2h[o4] = hi; d2l[o4] = lo;
    }
}

// ---------------- hist + scan (ticket) ----------------
__global__ void k_histscan(const int* __restrict__ pick) {
    __shared__ int h[NEXP];
    int tid = threadIdx.x;
    if (tid < NEXP) h[tid] = 0;
    __syncthreads();
    int n = blockIdx.x * blockDim.x + tid;
    if (n < NTOK) atomicAdd(&h[pick[n]], 1);
    __syncthreads();
    if (tid < NEXP && h[tid] > 0) atomicAdd(&g_counts[tid], h[tid]);
    __threadfence();
    __syncthreads();
    if (tid == 0) {
        if (atomicAdd(&g_tick, 1u) == gridDim.x - 1) {
            int s = 0;
            for (int e = 0; e < NEXP; ++e) {
                g_pbase[e]  = s;
                g_cursor[e] = s;
                int c = g_counts[e];
                s += ((c + TILE_M - 1) / TILE_M) * TILE_M;
            }
            g_pbase[NEXP] = s;
            g_tick = 0;
        }
    }
}

__global__ void k_scatter(const int* __restrict__ pick) {
    __shared__ int h[NEXP];
    __shared__ int base[NEXP];
    int tid = threadIdx.x;
    if (tid < NEXP) h[tid] = 0;
    __syncthreads();
    int n = blockIdx.x * blockDim.x + tid;
    int e = -1, r = 0;
    if (n < NTOK) { e = pick[n]; r = atomicAdd(&h[e], 1); }
    __syncthreads();
    if (tid < NEXP && h[tid] > 0) base[tid] = atomicAdd(&g_cursor[tid], h[tid]);
    __syncthreads();
    if (n < NTOK) g_sidx[base[e] + r] = n;
}

// ---------------- warp MMA helpers ----------------
__device__ __forceinline__ uint32_t smem_u32(const void* p) {
    uint32_t a;
    asm("{ .reg .u64 t; cvta.to.shared.u64 t, %1; cvt.u32.u64 %0, t; }"
        : "=r"(a) : "l"(p));
    return a;
}
__device__ __forceinline__ void ldsm4(uint32_t* r, uint32_t addr) {
    asm volatile("ldmatrix.sync.aligned.m8n8.x4.shared.b16 {%0,%1,%2,%3}, [%4];"
                 : "=r"(r[0]), "=r"(r[1]), "=r"(r[2]), "=r"(r[3]) : "r"(addr));
}
__device__ __forceinline__ void mma16816(float* d, const uint32_t* a,
                                         uint32_t b0, uint32_t b1) {
    asm volatile(
        "mma.sync.aligned.m16n8k16.row.col.f32.bf16.bf16.f32 "
        "{%0,%1,%2,%3}, {%4,%5,%6,%7}, {%8,%9}, {%0,%1,%2,%3};"
        : "+f"(d[0]), "+f"(d[1]), "+f"(d[2]), "+f"(d[3])
        : "r"(a[0]), "r"(a[1]), "r"(a[2]), "r"(a[3]), "r"(b0), "r"(b1));
}
#define CPA16(dst, src) \
    asm volatile("cp.async.cg.shared.global [%0], [%1], 16;" :: "r"(dst), "l"(src))
#define CPA_WAIT() \
    asm volatile("cp.async.commit_group;\ncp.async.wait_group 0;" ::: "memory")

// ---------------- fused main ----------------
__global__ __launch_bounds__(512, 1)
void k_main(const float* __restrict__ obs,
            const int*   __restrict__ htype,
            const int*   __restrict__ gsel,
            const float* __restrict__ b1,  const float* __restrict__ b2,
            const float* __restrict__ bc1, const float* __restrict__ bc2,
            float* __restrict__ out) {
    extern __shared__ char dsm[];
    __shared__ __align__(1024) unsigned char s_w2h[16 * 256];
    __shared__ __align__(1024) unsigned char s_w2l[16 * 256];
    __shared__ __align__(1024) unsigned char s_wch[16 * 256];
    __shared__ __align__(1024) unsigned char s_wcl[16 * 256];
    __shared__ float s_b1[HDIM], s_bc1[HDIM], s_b2[NACT];
    __shared__ int   s_idx[TILE_M];

    const int tid    = threadIdx.x;
    const int wid    = tid >> 5;
    const int lane   = tid & 31;
    const int lane15 = lane & 15;
    const int laneh  = lane >> 4;
    const int g      = lane >> 2;
    const int q4     = lane & 3;
    const int ts     = blockIdx.x * TILE_M;

    // every thread resolves its expert segment (uniform)
    int e = -1;
    #pragma unroll
    for (int q = 0; q < NEXP; ++q)
        if (ts >= g_pbase[q] && ts < g_pbase[q + 1]) e = q;
    if (e < 0) return;
    const int lim = g_pbase[e] + g_counts[e];
    const uint32_t db = smem_u32(dsm);

    // ---- weight tiles via cp.async (pre-swizzled in gmem) ----
    {
        const uint4* srcs[4] = {g_w1h + e * 2048, g_w1l + e * 2048, g_wch, g_wcl};
        #pragma unroll
        for (int it = 0; it < 16; ++it) {
            int idx = tid + it * 512;
            CPA16(db + B1H_OFF + idx * 16, srcs[idx >> 11] + (idx & 2047));
        }
        const uint4*   s2[4] = {g_w2h + e * 256, g_w2l + e * 256, g_wc2h, g_wc2l};
        const uint32_t d2[4] = {smem_u32(s_w2h), smem_u32(s_w2l),
                                smem_u32(s_wch), smem_u32(s_wcl)};
        #pragma unroll
        for (int it = 0; it < 2; ++it) {
            int idx = tid + it * 512;
            CPA16(d2[idx >> 8] + (idx & 255) * 16, s2[idx >> 8] + (idx & 255));
        }
    }

    // ---- token indices + aug chunk (k=120..127, exact in bf16, lo=0) ----
    if (tid < TILE_M) {
        int gi  = ts + tid;
        int tok = (gi < lim) ? g_sidx[gi] : -1;
        s_idx[tid] = tok;
        uint4 hi4 = {0u, 0u, 0u, 0u};
        if (tok >= 0) {
            int ht = htype[tok];
            int tI = tok >> 6;
            float av[8];
            av[0] = (float)ht;
            #pragma unroll
            for (int i = 0; i < NTP; ++i)
                av[1 + i] = (i == ht) ? -1.0f : (float)gsel[tI * NTP + i];
            av[6] = 0.0f; av[7] = 0.0f;
            uint32_t p[4];
            #pragma unroll
            for (int q = 0; q < 4; ++q) {
                __nv_bfloat162 h2 = __floats2bfloat162_rn(av[2 * q], av[2 * q + 1]);
                p[q] = reinterpret_cast<uint32_t&>(h2);
            }
            hi4 = make_uint4(p[0], p[1], p[2], p[3]);
        }
        uint32_t coff = (uint32_t)((15 ^ (tid & 7)) << 4);
        *(uint4*)(dsm + AH_OFF + tid * 256 + coff) = hi4;
        *(uint4*)(dsm + AL_OFF + tid * 256 + coff) = make_uint4(0u, 0u, 0u, 0u);
    }
    if (tid < HDIM) { s_b1[tid] = b1[e * HDIM + tid]; s_bc1[tid] = bc1[tid]; }
    if (tid < NACT) s_b2[tid] = b2[e * NACT + tid];
    __syncthreads();   // s_idx must be visible to ALL threads before A-stage

    // ---- A-stage: obs chunks (k = 0..119), hi/lo packed cvt ----
    #pragma unroll
    for (int it = 0; it < 4; ++it) {
        int idx = tid + it * 512;           // (row, chunk) over 128x16
        int row = idx >> 4, c = idx & 15;
        if (c == 15) continue;              // aug chunk already written
        int tok = s_idx[row];
        uint4 hi4 = {0u,0u,0u,0u}, lo4 = {0u,0u,0u,0u};
        if (tok >= 0) {
            const float4* src = (const float4*)(obs + (size_t)tok * RAWOB + c * 8);
            float4 f0 = src[0], f1 = src[1];
            uint32_t h, l;
            cvt_hilo(f0.x, f0.y, h, l); hi4.x = h; lo4.x = l;
            cvt_hilo(f0.z, f0.w, h, l); hi4.y = h; lo4.y = l;
            cvt_hilo(f1.x, f1.y, h, l); hi4.z = h; lo4.z = l;
            cvt_hilo(f1.z, f1.w, h, l); hi4.w = h; lo4.w = l;
        }
        uint32_t off = (uint32_t)(row * 256 + ((c ^ (row & 7)) << 4));
        *(uint4*)(dsm + AH_OFF + off) = hi4;
        *(uint4*)(dsm + AL_OFF + off) = lo4;
    }
    CPA_WAIT();
    __syncthreads();

    // ---- mainloop: 128x128x128 bf16 hi/lo (3 passes), actor | critic ----
    const int isActor = (wid < 8);
    const int wq = wid & 7;
    const int m0 = (wq & 3) * 32;
    const int n0 = (wq >> 2) * 64;

    const int arow0 = m0 + lane15, arow1 = arow0 + 16;
    const uint32_t aoff0 = arow0 * 256, aoff1 = arow1 * 256;
    const int r7a0 = arow0 & 7, r7a1 = arow1 & 7;
    uint32_t boffv[4]; int r7b[4];
    #pragma unroll
    for (int qb = 0; qb < 4; ++qb) {
        int br = n0 + qb * 16 + lane15;
        boffv[qb] = br * 256; r7b[qb] = br & 7;
    }

    float acc[2][8][4];
    #pragma unroll
    for (int i = 0; i < 2; ++i)
        #pragma unroll
        for (int j = 0; j < 8; ++j)
            #pragma unroll
            for (int c = 0; c < 4; ++c) acc[i][j][c] = 0.0f;

    const uint32_t aB[3] = {db + AH_OFF, db + AH_OFF, db + AL_OFF};
    const uint32_t bB[3] = {
        isActor ? db + B1H_OFF : db + BCH_OFF,
        isActor ? db + B1L_OFF : db + BCL_OFF,
        isActor ? db + B1H_OFF : db + BCH_OFF};

    #pragma unroll
    for (int p = 0; p < 3; ++p) {
        const uint32_t ab = aB[p], bb = bB[p];
        #pragma unroll
        for (int ks = 0; ks < 8; ++ks) {
            const int c0 = 2 * ks + laneh;
            uint32_t af0[4], af1[4];
            ldsm4(af0, ab + aoff0 + (uint32_t)((c0 ^ r7a0) << 4));
            ldsm4(af1, ab + aoff1 + (uint32_t)((c0 ^ r7a1) << 4));
            #pragma unroll
            for (int qb = 0; qb < 4; ++qb) {
                uint32_t bf[4];
                ldsm4(bf, bb + boffv[qb] + (uint32_t)((c0 ^ r7b[qb]) << 4));
                mma16816(acc[0][2 * qb],     af0, bf[0], bf[2]);
                mma16816(acc[0][2 * qb + 1], af0, bf[1], bf[3]);
                mma16816(acc[1][2 * qb],     af1, bf[0], bf[2]);
                mma16816(acc[1][2 * qb + 1], af1, bf[1], bf[3]);
            }
        }
    }
    __syncthreads();

    // ---- bias + relu, hidden hi/lo writeback (actor->AH/AL, critic->B1H/B1L)
    {
        char* hH = dsm + (isActor ? AH_OFF  : B1H_OFF);
        char* hL = dsm + (isActor ? AL_OFF  : B1L_OFF);
        const float* bs = isActor ? s_b1 : s_bc1;
        #pragma unroll
        for (int mt = 0; mt < 2; ++mt) {
            #pragma unroll
            for (int nf = 0; nf < 8; ++nf) {
                const int col = n0 + 8 * nf + 2 * q4;
                const float bA = bs[col], bBv = bs[col + 1];
                const int r0 = m0 + 16 * mt + g, r1 = r0 + 8;
                float v0 = fmaxf(acc[mt][nf][0] + bA, 0.0f);
                float v1 = fmaxf(acc[mt][nf][1] + bBv, 0.0f);
                uint32_t hi, lo; cvt_hilo(v0, v1, hi, lo);
                uint32_t off = toff(r0, col);
                *(uint32_t*)(hH + off) = hi;
                *(uint32_t*)(hL + off) = lo;
                v0 = fmaxf(acc[mt][nf][2] + bA, 0.0f);
                v1 = fmaxf(acc[mt][nf][3] + bBv, 0.0f);
                cvt_hilo(v0, v1, hi, lo);
                off = toff(r1, col);
                *(uint32_t*)(hH + off) = hi;
                *(uint32_t*)(hL + off) = lo;
            }
        }
    }
    __syncthreads();

    // ---- phase 2: logits = h@W2 (actor), value = h@Wc2 (critic), via MMA ----
    {
        const int arow = wq * 16 + lane15;
        const uint32_t aoff = arow * 256;
        const int r7 = arow & 7;
        const uint32_t boffp = lane15 * 256;
        const int r7p = lane15 & 7;

        const uint32_t a2B[3] = {
            isActor ? db + AH_OFF : db + B1H_OFF,
            isActor ? db + AH_OFF : db + B1H_OFF,
            isActor ? db + AL_OFF : db + B1L_OFF};
        const uint32_t w2h = smem_u32(s_w2h), w2l = smem_u32(s_w2l);
        const uint32_t wch = smem_u32(s_wch), wcl = smem_u32(s_wcl);
        const uint32_t b2B[3] = {
            isActor ? w2h : wch, isActor ? w2l : wcl, isActor ? w2h : wch};

        float ac2[2][4];
        #pragma unroll
        for (int i = 0; i < 2; ++i)
            #pragma unroll
            for (int c = 0; c < 4; ++c) ac2[i][c] = 0.0f;

        #pragma unroll
        for (int p = 0; p < 3; ++p) {
            #pragma unroll
            for (int ks = 0; ks < 8; ++ks) {
                const int c0 = 2 * ks + laneh;
                uint32_t af[4], bf[4];
                ldsm4(af, a2B[p] + aoff + (uint32_t)((c0 ^ r7) << 4));
                ldsm4(bf, b2B[p] + boffp + (uint32_t)((c0 ^ r7p) << 4));
                mma16816(ac2[0], af, bf[0], bf[2]);
                if (isActor) mma16816(ac2[1], af, bf[1], bf[3]);
            }
        }

        const int r0 = wq * 16 + g, r1 = r0 + 8;
        const int tok0 = s_idx[r0], tok1 = s_idx[r1];
        if (isActor) {
            #pragma unroll
            for (int nf = 0; nf < 2; ++nf) {
                const int cl = 8 * nf + 2 * q4;
                const float bA = s_b2[cl], bBv = s_b2[cl + 1];
                if (tok0 >= 0) {
                    float2 v = {ac2[nf][0] + bA, ac2[nf][1] + bBv};
                    *(float2*)(out + (size_t)tok0 * NACT + cl) = v;
                }
                if (tok1 >= 0) {
                    float2 v = {ac2[nf][2] + bA, ac2[nf][3] + bBv};
                    *(float2*)(out + (size_t)tok1 * NACT + cl) = v;
                }
            }
        } else if (q4 == 0) {
            const float bcv = bc2[0];
            if (tok0 >= 0) out[(size_t)NTOK * NACT + tok0] = ac2[0][0] + bcv;
            if (tok1 >= 0) out[(size_t)NTOK * NACT + tok1] = ac2[0][2] + bcv;
        }
    }
}

// ---------------- launch ----------------
extern "C" void kernel_launch(void* const* d_in, const int* in_sizes, int n_in,
                              void* d_out, int out_size) {
    const float* obs   = (const float*)d_in[0];
    const int*   pick  = (const int*)  d_in[1];
    const int*   htype = (const int*)  d_in[2];
    const int*   gsel  = (const int*)  d_in[3];
    const float* W1    = (const float*)d_in[4];
    const float* b1    = (const float*)d_in[5];
    const float* W2    = (const float*)d_in[6];
    const float* b2    = (const float*)d_in[7];
    const float* Wc1   = (const float*)d_in[8];
    const float* bc1   = (const float*)d_in[9];
    const float* Wc2   = (const float*)d_in[10];
    const float* bc2   = (const float*)d_in[11];
    float* out = (float*)d_out;

    cudaFuncSetAttribute(k_main, cudaFuncAttributeMaxDynamicSharedMemorySize, DYN_SMEM);

    k_prep    <<<NEXP + 1, 256>>>(W1, W2, Wc1, Wc2);
    k_histscan<<<(NTOK + 255) / 256, 256>>>(pick);
    k_scatter <<<(NTOK + 255) / 256, 256>>>(pick);
    k_main    <<<NTILES, 512, DYN_SMEM>>>(obs, htype, gsel,
                                          b1, b2, bc1, bc2, out);
}

// round 7
// speedup vs baseline: 13.7960x; 1.7901x over previous
#include <cuda_runtime.h>
#include <cuda_fp16.h>
#include <cstdint>

// ---------------- problem constants ----------------
#define NTOK   131072
#define RAWOB  120
#define NTP    5
#define NEXP   10
#define DDIM   126
#define HDIM   128
#define NACT   16
#define TILE_M 128
#define NPAD   (NTOK + NEXP * TILE_M) // 132352
#define NTILES (NPAD / TILE_M)        // 1034

// dynamic smem: three 128x128 fp16 tiles (32KB each)
#define A_OFF   0
#define BH_OFF  32768
#define BL_OFF  65536
#define DYN_SMEM 98304

// ---------------- scratch ----------------
__device__ int g_counts[NEXP];
__device__ int g_cursor[NEXP];
__device__ int g_pbase[NEXP + 1];
__device__ int g_sidx[NPAD];
__device__ unsigned int g_tick;

// pre-swizzled fp16 hi/lo weight tiles; slot NEXP = critic Wc1
__device__ uint4 g_w1h[(NEXP + 1) * 2048];  // 32KB per net
__device__ uint4 g_w1l[(NEXP + 1) * 2048];
__device__ uint4 g_w2h[NEXP * 256];         // 4KB per expert (16x128)
__device__ uint4 g_w2l[NEXP * 256];

// tile element byte offset: 256B rows, 16B chunks XOR-swizzled by row
__device__ __forceinline__ uint32_t toff(int row, int k) {
    return (uint32_t)(row * 256 + (((k >> 3) ^ (row & 7)) << 4) + (k & 7) * 2);
}
__device__ __forceinline__ void cvt_hilo(float a, float b, uint32_t& hi, uint32_t& lo) {
    __half2 h2 = __floats2half2_rn(a, b);
    float2 bk = __half22float2(h2);
    __half2 l2 = __floats2half2_rn(a - bk.x, b - bk.y);
    hi = reinterpret_cast<uint32_t&>(h2);
    lo = reinterpret_cast<uint32_t&>(l2);
}
__device__ __forceinline__ uint32_t cvt_h2(float a, float b) {
    __half2 h2 = __floats2half2_rn(a, b);
    return reinterpret_cast<uint32_t&>(h2);
}

// ---------------- k_init ----------------
__global__ void k_init() {
    int i = threadIdx.x;
    if (i < NEXP) { g_counts[i] = 0; g_cursor[i] = 0; }
    if (i == 31) g_tick = 0;
}

// ---------------- hist + scan (ticket) ----------------
__global__ void k_histscan(const int* __restrict__ pick) {
    __shared__ int h[NEXP];
    int tid = threadIdx.x;
    if (tid < NEXP) h[tid] = 0;
    __syncthreads();
    int n = blockIdx.x * blockDim.x + tid;
    if (n < NTOK) atomicAdd(&h[pick[n]], 1);
    __syncthreads();
    if (tid < NEXP && h[tid] > 0) atomicAdd(&g_counts[tid], h[tid]);
    __threadfence();
    __syncthreads();
    if (tid == 0) {
        if (atomicAdd(&g_tick, 1u) == gridDim.x - 1) {
            int s = 0;
            for (int e = 0; e < NEXP; ++e) {
                g_pbase[e]  = s;
                g_cursor[e] = s;
                int c = g_counts[e];
                s += ((c + TILE_M - 1) / TILE_M) * TILE_M;
            }
            g_pbase[NEXP] = s;
            g_tick = 0;
        }
    }
}

// ---------------- scatter (blocks < 512) + weight prep (blocks >= 512) ----
__global__ void k_scatter_prep(const int* __restrict__ pick,
                               const float* __restrict__ W1,
                               const float* __restrict__ W2,
                               const float* __restrict__ Wc1) {
    const int tid = threadIdx.x;
    if (blockIdx.x < 512) {
        __shared__ int h[NEXP];
        __shared__ int base[NEXP];
        if (tid < NEXP) h[tid] = 0;
        __syncthreads();
        int n = blockIdx.x * blockDim.x + tid;
        int e = -1, r = 0;
        if (n < NTOK) { e = pick[n]; r = atomicAdd(&h[e], 1); }
        __syncthreads();
        if (tid < NEXP && h[tid] > 0) base[tid] = atomicAdd(&g_cursor[tid], h[tid]);
        __syncthreads();
        if (n < NTOK) g_sidx[base[e] + r] = n;
        return;
    }
    // weight conversion: we = 0..NEXP (NEXP = critic)
    const int we = blockIdx.x - 512;
    uint32_t* d1h = (uint32_t*)g_w1h + we * 8192;
    uint32_t* d1l = (uint32_t*)g_w1l + we * 8192;
    const float* w1p = (we < NEXP) ? W1 + (size_t)we * DDIM * HDIM : Wc1;
    for (int it = tid; it < 64 * 128; it += 256) {   // (kpair, n)
        int n = it & 127, kp = it >> 7, k0 = kp * 2;
        float a0 = (k0     < DDIM) ? w1p[k0 * HDIM + n]       : 0.0f;
        float a1 = (k0 + 1 < DDIM) ? w1p[(k0 + 1) * HDIM + n] : 0.0f;
        uint32_t hi, lo; cvt_hilo(a0, a1, hi, lo);
        uint32_t o4 = toff(n, k0) >> 2;
        d1h[o4] = hi; d1l[o4] = lo;
    }
    if (we < NEXP) {
        uint32_t* d2h = (uint32_t*)g_w2h + we * 1024;
        uint32_t* d2l = (uint32_t*)g_w2l + we * 1024;
        for (int it = tid; it < 16 * 64; it += 256) { // (o, jpair)
            int o = it >> 6, jp = it & 63, j0 = jp * 2;
            float a = W2[((size_t)we * HDIM + j0) * NACT + o];
            float b = W2[((size_t)we * HDIM + j0 + 1) * NACT + o];
            uint32_t hi, lo; cvt_hilo(a, b, hi, lo);
            uint32_t o4 = toff(o, j0) >> 2;
            d2h[o4] = hi; d2l[o4] = lo;
        }
    }
}

// ---------------- warp MMA helpers ----------------
__device__ __forceinline__ uint32_t smem_u32(const void* p) {
    uint32_t a;
    asm("{ .reg .u64 t; cvta.to.shared.u64 t, %1; cvt.u32.u64 %0, t; }"
        : "=r"(a) : "l"(p));
    return a;
}
__device__ __forceinline__ void ldsm4(uint32_t* r, uint32_t addr) {
    asm volatile("ldmatrix.sync.aligned.m8n8.x4.shared.b16 {%0,%1,%2,%3}, [%4];"
                 : "=r"(r[0]), "=r"(r[1]), "=r"(r[2]), "=r"(r[3]) : "r"(addr));
}
__device__ __forceinline__ void mma16816(float* d, const uint32_t* a,
                                         uint32_t b0, uint32_t b1) {
    asm volatile(
        "mma.sync.aligned.m16n8k16.row.col.f32.f16.f16.f32 "
        "{%0,%1,%2,%3}, {%4,%5,%6,%7}, {%8,%9}, {%0,%1,%2,%3};"
        : "+f"(d[0]), "+f"(d[1]), "+f"(d[2]), "+f"(d[3])
        : "r"(a[0]), "r"(a[1]), "r"(a[2]), "r"(a[3]), "r"(b0), "r"(b1));
}
#define CPA16(dst, src) \
    asm volatile("cp.async.cg.shared.global [%0], [%1], 16;" :: "r"(dst), "l"(src))
#define CPA_WAIT() \
    asm volatile("cp.async.commit_group;\ncp.async.wait_group 0;" ::: "memory")

// ---------------- fused main: one CTA = one (tile, net) pair ----------------
// blockIdx.x even -> actor tile, odd -> critic tile; tile = blockIdx.x >> 1.
__global__ __launch_bounds__(256, 2)
void k_main(const float* __restrict__ obs,
            const int*   __restrict__ htype,
            const int*   __restrict__ gsel,
            const float* __restrict__ b1,  const float* __restrict__ b2,
            const float* __restrict__ bc1, const float* __restrict__ bc2,
            const float* __restrict__ Wc2,
            float* __restrict__ out) {
    extern __shared__ char dsm[];
    __shared__ __align__(1024) unsigned char s_w2h[16 * 256];
    __shared__ __align__(1024) unsigned char s_w2l[16 * 256];
    __shared__ float s_b1[HDIM], s_bc1[HDIM], s_wc2[HDIM], s_val[TILE_M], s_b2[NACT];
    __shared__ int   s_idx[TILE_M];

    const int tid    = threadIdx.x;
    const int wid    = tid >> 5;          // 0..7
    const int lane   = tid & 31;
    const int lane15 = lane & 15;
    const int laneh  = lane >> 4;
    const int g      = lane >> 2;
    const int q4     = lane & 3;
    const int tile   = blockIdx.x >> 1;
    const int isCr   = blockIdx.x & 1;
    const int ts     = tile * TILE_M;

    int e = -1;
    #pragma unroll
    for (int q = 0; q < NEXP; ++q)
        if (ts >= g_pbase[q] && ts < g_pbase[q + 1]) e = q;
    if (e < 0) return;
    const int lim = g_pbase[e] + g_counts[e];
    const uint32_t db = smem_u32(dsm);

    // ---- B tiles via cp.async (pre-swizzled fp16 hi/lo) ----
    {
        const int we = isCr ? NEXP : e;
        const uint4* sh = g_w1h + we * 2048;
        const uint4* sl = g_w1l + we * 2048;
        #pragma unroll
        for (int it = 0; it < 8; ++it) {
            int idx = tid + it * 256;
            CPA16(db + BH_OFF + idx * 16, sh + idx);
        }
        #pragma unroll
        for (int it = 0; it < 8; ++it) {
            int idx = tid + it * 256;
            CPA16(db + BL_OFF + idx * 16, sl + idx);
        }
        if (!isCr) {
            const uint32_t w2hA = smem_u32(s_w2h), w2lA = smem_u32(s_w2l);
            const uint4* s2h = g_w2h + e * 256;
            const uint4* s2l = g_w2l + e * 256;
            if (tid < 256) {
                CPA16(w2hA + tid * 16, s2h + tid);
                CPA16(w2lA + tid * 16, s2l + tid);
            }
        }
    }

    // ---- token indices + aug chunk (k=120..127, exact in fp16) ----
    if (tid < TILE_M) {
        int gi  = ts + tid;
        int tok = (gi < lim) ? g_sidx[gi] : -1;
        s_idx[tid] = tok;
        uint4 a4 = {0u, 0u, 0u, 0u};
        if (tok >= 0) {
            int ht = htype[tok];
            int tI = tok >> 6;
            float av[6];
            av[0] = (float)ht;
            #pragma unroll
            for (int i = 0; i < NTP; ++i)
                av[1 + i] = (i == ht) ? -1.0f : (float)gsel[tI * NTP + i];
            a4.x = cvt_h2(av[0], av[1]);
            a4.y = cvt_h2(av[2], av[3]);
            a4.z = cvt_h2(av[4], av[5]);
            a4.w = 0u;
        }
        *(uint4*)(dsm + A_OFF + tid * 256 + ((15 ^ (tid & 7)) << 4)) = a4;
        s_b1[tid]  = b1[e * HDIM + tid];
        s_bc1[tid] = bc1[tid];
        s_wc2[tid] = Wc2[tid];
        s_val[tid] = 0.0f;
    }
    if (tid < NACT) s_b2[tid] = b2[e * NACT + tid];
    __syncthreads();   // s_idx visible to all before A-stage

    // ---- A-stage: obs chunks (k = 0..119), single fp16 ----
    #pragma unroll
    for (int it = 0; it < 8; ++it) {
        int idx = tid + it * 256;            // (row, chunk) over 128x16
        int row = idx >> 4, c = idx & 15;
        if (c == 15) continue;               // aug chunk already written
        int tok = s_idx[row];
        uint4 a4 = {0u, 0u, 0u, 0u};
        if (tok >= 0) {
            const float4* src = (const float4*)(obs + (size_t)tok * RAWOB + c * 8);
            float4 f0 = src[0], f1 = src[1];
            a4.x = cvt_h2(f0.x, f0.y);
            a4.y = cvt_h2(f0.z, f0.w);
            a4.z = cvt_h2(f1.x, f1.y);
            a4.w = cvt_h2(f1.z, f1.w);
        }
        *(uint4*)(dsm + A_OFF + row * 256 + ((c ^ (row & 7)) << 4)) = a4;
    }
    CPA_WAIT();
    __syncthreads();

    // ---- mainloop: D = A*(WH) + A*(WL), A fragments hoisted ----
    const int m0 = (wid & 3) * 32;
    const int n0 = (wid >> 2) * 64;
    const int arow0 = m0 + lane15, arow1 = arow0 + 16;
    const uint32_t aoff0 = arow0 * 256, aoff1 = arow1 * 256;
    const int r7a0 = arow0 & 7, r7a1 = arow1 & 7;
    uint32_t boffv[4]; int r7b[4];
    #pragma unroll
    for (int qb = 0; qb < 4; ++qb) {
        int br = n0 + qb * 16 + lane15;
        boffv[qb] = br * 256; r7b[qb] = br & 7;
    }

    float acc[2][8][4];
    #pragma unroll
    for (int i = 0; i < 2; ++i)
        #pragma unroll
        for (int j = 0; j < 8; ++j)
            #pragma unroll
            for (int c = 0; c < 4; ++c) acc[i][j][c] = 0.0f;

    #pragma unroll
    for (int ks = 0; ks < 8; ++ks) {
        const int c0 = 2 * ks + laneh;
        uint32_t af0[4], af1[4];
        ldsm4(af0, db + A_OFF + aoff0 + (uint32_t)((c0 ^ r7a0) << 4));
        ldsm4(af1, db + A_OFF + aoff1 + (uint32_t)((c0 ^ r7a1) << 4));
        #pragma unroll
        for (int p = 0; p < 2; ++p) {
            const uint32_t bb = db + (p ? BL_OFF : BH_OFF);
            #pragma unroll
            for (int qb = 0; qb < 4; ++qb) {
                uint32_t bf[4];
                ldsm4(bf, bb + boffv[qb] + (uint32_t)((c0 ^ r7b[qb]) << 4));
                mma16816(acc[0][2 * qb],     af0, bf[0], bf[2]);
                mma16816(acc[0][2 * qb + 1], af0, bf[1], bf[3]);
                mma16816(acc[1][2 * qb],     af1, bf[0], bf[2]);
                mma16816(acc[1][2 * qb + 1], af1, bf[1], bf[3]);
            }
        }
    }
    __syncthreads();   // all A/B reads done

    if (isCr) {
        // ---- critic epilogue: value from fp32 accumulators ----
        #pragma unroll
        for (int mt = 0; mt < 2; ++mt) {
            float p0 = 0.0f, p1 = 0.0f;
            #pragma unroll
            for (int nf = 0; nf < 8; ++nf) {
                const int col = n0 + 8 * nf + 2 * q4;
                const float w0 = s_wc2[col], w1 = s_wc2[col + 1];
                const float c0v = s_bc1[col], c1v = s_bc1[col + 1];
                p0 += fmaxf(acc[mt][nf][0] + c0v, 0.0f) * w0
                    + fmaxf(acc[mt][nf][1] + c1v, 0.0f) * w1;
                p1 += fmaxf(acc[mt][nf][2] + c0v, 0.0f) * w0
                    + fmaxf(acc[mt][nf][3] + c1v, 0.0f) * w1;
            }
            p0 += __shfl_xor_sync(0xffffffffu, p0, 1);
            p0 += __shfl_xor_sync(0xffffffffu, p0, 2);
            p1 += __shfl_xor_sync(0xffffffffu, p1, 1);
            p1 += __shfl_xor_sync(0xffffffffu, p1, 2);
            if (q4 == 0) {
                atomicAdd(&s_val[m0 + 16 * mt + g],     p0);
                atomicAdd(&s_val[m0 + 16 * mt + g + 8], p1);
            }
        }
        __syncthreads();
        if (tid < TILE_M) {
            int tok = s_idx[tid];
            if (tok >= 0) out[(size_t)NTOK * NACT + tok] = s_val[tid] + bc2[0];
        }
        return;
    }

    // ---- actor: hidden writeback (hi -> A region, lo -> BH region) ----
    #pragma unroll
    for (int mt = 0; mt < 2; ++mt) {
        #pragma unroll
        for (int nf = 0; nf < 8; ++nf) {
            const int col = n0 + 8 * nf + 2 * q4;
            const float bA = s_b1[col], bBv = s_b1[col + 1];
            const int r0 = m0 + 16 * mt + g, r1 = r0 + 8;
            uint32_t hi, lo;
            cvt_hilo(fmaxf(acc[mt][nf][0] + bA, 0.0f),
                     fmaxf(acc[mt][nf][1] + bBv, 0.0f), hi, lo);
            uint32_t off = toff(r0, col);
            *(uint32_t*)(dsm + A_OFF + off)  = hi;
            *(uint32_t*)(dsm + BH_OFF + off) = lo;
            cvt_hilo(fmaxf(acc[mt][nf][2] + bA, 0.0f),
                     fmaxf(acc[mt][nf][3] + bBv, 0.0f), hi, lo);
            off = toff(r1, col);
            *(uint32_t*)(dsm + A_OFF + off)  = hi;
            *(uint32_t*)(dsm + BH_OFF + off) = lo;
        }
    }
    __syncthreads();

    // ---- actor phase 2: logits = h @ W2 + b2 (3 passes: hh*wh + hh*wl + hl*wh)
    {
        const int arow = wid * 16 + lane15;
        const uint32_t aoff = arow * 256;
        const int r7 = arow & 7;
        const uint32_t boffp = lane15 * 256;
        const int r7p = lane15 & 7;
        const uint32_t w2hA = smem_u32(s_w2h), w2lA = smem_u32(s_w2l);
        const uint32_t aP[3] = {db + A_OFF, db + A_OFF, db + BH_OFF};
        const uint32_t bP[3] = {w2hA, w2lA, w2hA};

        float ac2[2][4];
        #pragma unroll
        for (int i = 0; i < 2; ++i)
            #pragma unroll
            for (int c = 0; c < 4; ++c) ac2[i][c] = 0.0f;

        #pragma unroll
        for (int p = 0; p < 3; ++p) {
            #pragma unroll
            for (int ks = 0; ks < 8; ++ks) {
                const int c0 = 2 * ks + laneh;
                uint32_t af[4], bf[4];
                ldsm4(af, aP[p] + aoff + (uint32_t)((c0 ^ r7) << 4));
                ldsm4(bf, bP[p] + boffp + (uint32_t)((c0 ^ r7p) << 4));
                mma16816(ac2[0], af, bf[0], bf[2]);
                mma16816(ac2[1], af, bf[1], bf[3]);
            }
        }

        const int r0 = wid * 16 + g, r1 = r0 + 8;
        const int tok0 = s_idx[r0], tok1 = s_idx[r1];
        #pragma unroll
        for (int nf = 0; nf < 2; ++nf) {
            const int cl = 8 * nf + 2 * q4;
            const float bA = s_b2[cl], bBv = s_b2[cl + 1];
            if (tok0 >= 0) {
                float2 v = {ac2[nf][0] + bA, ac2[nf][1] + bBv};
                *(float2*)(out + (size_t)tok0 * NACT + cl) = v;
            }
            if (tok1 >= 0) {
                float2 v = {ac2[nf][2] + bA, ac2[nf][3] + bBv};
                *(float2*)(out + (size_t)tok1 * NACT + cl) = v;
            }
        }
    }
}

// ---------------- launch ----------------
extern "C" void kernel_launch(void* const* d_in, const int* in_sizes, int n_in,
                              void* d_out, int out_size) {
    const float* obs   = (const float*)d_in[0];
    const int*   pick  = (const int*)  d_in[1];
    const int*   htype = (const int*)  d_in[2];
    const int*   gsel  = (const int*)  d_in[3];
    const float* W1    = (const float*)d_in[4];
    const float* b1    = (const float*)d_in[5];
    const float* W2    = (const float*)d_in[6];
    const float* b2    = (const float*)d_in[7];
    const float* Wc1   = (const float*)d_in[8];
    const float* bc1   = (const float*)d_in[9];
    const float* Wc2   = (const float*)d_in[10];
    const float* bc2   = (const float*)d_in[11];
    float* out = (float*)d_out;

    cudaFuncSetAttribute(k_main, cudaFuncAttributeMaxDynamicSharedMemorySize, DYN_SMEM);

    k_init        <<<1, 32>>>();
    k_histscan    <<<512, 256>>>(pick);
    k_scatter_prep<<<512 + NEXP + 1, 256>>>(pick, W1, W2, Wc1);
    k_main        <<<2 * NTILES, 256, DYN_SMEM>>>(obs, htype, gsel,
                                                  b1, b2, bc1, bc2, Wc2, out);
}